// round 9
// baseline (speedup 1.0000x reference)
#include <cuda_runtime.h>
#include <cuda_bf16.h>
#include <math_constants.h>
#include <cstdint>

#define DIM     128
#define QB      128
#define NB      64
#define NSPLIT  18
#define LSEL    8
#define LSTR    9            // list stride (floats) -> conflict-free accesses
#define SHORT   20
#define KSEL    10
#define MAXB    2048
#define MAXN    100000
#define MAXNP   100992
#define CAND    (NSPLIT * LSEL)
#define NT      256
#define CAP     2048

// ---- dynamic smem layout ----
#define OFF_A    0            // 128x128 bf16 queries, swizzled       32KB
#define OFF_B0   32768        // candidate tile buf0 (64x256B)        16KB
#define OFF_B1   49152        // candidate tile buf1                  16KB
#define OFF_C0   65536        // 64 floats c[n] buf0
#define OFF_C1   65792        // 64 floats c[n] buf1
#define OFF_KEY  66048        // 128 * LSTR floats (per-query lists)
#define OFF_IDX  (OFF_KEY + 128 * LSTR * 4)
#define OFF_BK   (OFF_IDX + 128 * LSTR * 4)      // survivor keys   8KB
#define OFF_BM   (OFF_BK + CAP * 4)              // survivor meta   8KB
#define OFF_CNT  (OFF_BM + CAP * 4)
#define SMEM_DYN (OFF_CNT + 128)

// ---------------- device scratch ----------------
__device__ float          g_wmax;
__device__ float          g_c[MAXNP];
__device__ __nv_bfloat16  g_Xbf[(size_t)MAXNP * DIM];
__device__ float          g_keys[(size_t)MAXB * CAND];
__device__ int            g_idxs[(size_t)MAXB * CAND];

// ---------------- helpers ----------------
__device__ __forceinline__ uint32_t smem_u32(const void* p) {
    uint32_t a;
    asm("{ .reg .u64 t; cvta.to.shared.u64 t, %1; cvt.u32.u64 %0, t; }" : "=r"(a) : "l"(p));
    return a;
}
__device__ __forceinline__ void ldsm4(uint32_t& r0, uint32_t& r1, uint32_t& r2, uint32_t& r3,
                                      uint32_t addr) {
    asm volatile("ldmatrix.sync.aligned.m8n8.x4.shared.b16 {%0,%1,%2,%3}, [%4];"
                 : "=r"(r0), "=r"(r1), "=r"(r2), "=r"(r3) : "r"(addr));
}
__device__ __forceinline__ void mma16816(float* c, const uint32_t* a, uint32_t b0, uint32_t b1) {
    asm volatile("mma.sync.aligned.m16n8k16.row.col.f32.bf16.bf16.f32 "
                 "{%0,%1,%2,%3}, {%4,%5,%6,%7}, {%8,%9}, {%0,%1,%2,%3};"
                 : "+f"(c[0]), "+f"(c[1]), "+f"(c[2]), "+f"(c[3])
                 : "r"(a[0]), "r"(a[1]), "r"(a[2]), "r"(a[3]), "r"(b0), "r"(b1));
}
__device__ __forceinline__ void cpa16(uint32_t dst, const void* src) {
    asm volatile("cp.async.cg.shared.global [%0], [%1], 16;"
                 :: "r"(dst), "l"((size_t)__cvta_generic_to_global(src)) : "memory");
}
__device__ __forceinline__ void cpa4(uint32_t dst, const void* src) {
    asm volatile("cp.async.ca.shared.global [%0], [%1], 4;"
                 :: "r"(dst), "l"((size_t)__cvta_generic_to_global(src)) : "memory");
}
#define CP_COMMIT() asm volatile("cp.async.commit_group;" ::: "memory")
#define CP_WAIT(n)  asm volatile("cp.async.wait_group %0;" :: "n"(n) : "memory")

__device__ __forceinline__ uint32_t bf2pack(float x, float y) {
    __nv_bfloat162 v = __floats2bfloat162_rn(x, y);
    return *(uint32_t*)&v;
}

// ---------------- init / wmax ----------------
__global__ void init_kernel() { g_wmax = 0.0f; }

__global__ void wmax_kernel(const float* __restrict__ w, int n) {
    float m = 0.0f;
    for (int i = blockIdx.x * blockDim.x + threadIdx.x; i < n; i += gridDim.x * blockDim.x)
        m = fmaxf(m, w[i]);
    #pragma unroll
    for (int o = 16; o; o >>= 1) m = fmaxf(m, __shfl_xor_sync(0xffffffffu, m, o));
    __shared__ float sm[32];
    int lane = threadIdx.x & 31, wid = threadIdx.x >> 5;
    if (lane == 0) sm[wid] = m;
    __syncthreads();
    if (wid == 0) {
        m = (lane < (int)(blockDim.x >> 5)) ? sm[lane] : 0.0f;
        #pragma unroll
        for (int o = 16; o; o >>= 1) m = fmaxf(m, __shfl_xor_sync(0xffffffffu, m, o));
        if (lane == 0) atomicMax((int*)&g_wmax, __float_as_int(m));  // vals >= 0
    }
}

// ---------------- prep: c[n] + bf16 convert, padded tail ----------------
__global__ void prep_kernel(const float* __restrict__ X, const float* __restrict__ w,
                            int n, int padn) {
    int i = blockIdx.x * blockDim.x + threadIdx.x;
    if (i >= padn) return;
    __nv_bfloat162* dst = (__nv_bfloat162*)(g_Xbf + (size_t)i * DIM);
    if (i >= n) {
        for (int j = 0; j < DIM / 2; j++) dst[j] = __floats2bfloat162_rn(0.f, 0.f);
        g_c[i] = CUDART_INF_F;
        return;
    }
    const float4* xr = (const float4*)(X + (size_t)i * DIM);
    float s = 0.0f;
    #pragma unroll
    for (int j = 0; j < DIM / 4; j++) {
        float4 v = xr[j];
        s = fmaf(v.x, v.x, s); s = fmaf(v.y, v.y, s);
        s = fmaf(v.z, v.z, s); s = fmaf(v.w, v.w, s);
        dst[2 * j + 0] = __floats2bfloat162_rn(v.x, v.y);
        dst[2 * j + 1] = __floats2bfloat162_rn(v.z, v.w);
    }
    g_c[i] = s + (g_wmax - w[i]);
}

// owner-side insertion into per-query sorted smem list
__device__ __forceinline__ void list_insert(float* mkq, int* miq, float key, int n) {
    const float k7 = mkq[LSEL - 1];
    const int   n7 = miq[LSEL - 1];
    if (key < k7 || (key == k7 && n < n7)) {
        int p = LSEL - 1;
        #pragma unroll 1
        while (p > 0 && (mkq[p - 1] > key || (mkq[p - 1] == key && miq[p - 1] > n))) {
            mkq[p] = mkq[p - 1]; miq[p] = miq[p - 1]; p--;
        }
        mkq[p] = key; miq[p] = n;
    }
}

// ---------------- main: mma.sync GEMM + survivor-buffer top-LSEL ----------------
__global__ void __launch_bounds__(NT, 2)
topk_kernel(const float* __restrict__ xt, int per, int ntiles) {
    extern __shared__ unsigned char sraw[];
    unsigned char* s = sraw;
    const uint32_t sb = smem_u32(s);

    const int tid = threadIdx.x;
    const int l = tid & 31, wid = tid >> 5;
    const int wm = wid >> 2, wn = wid & 3;          // warp grid 2 x 4 (64 x 16 per warp)
    const int qbase = blockIdx.x * QB;
    const int split = blockIdx.y;
    const int sBeg = split * per;
    const int nEnd = sBeg + per;

    float* sKey = (float*)(s + OFF_KEY);
    int*   sIdx = (int*)(s + OFF_IDX);
    float* sBK  = (float*)(s + OFF_BK);
    int*   sBM  = (int*)(s + OFF_BM);
    int*   sCnt = (int*)(s + OFF_CNT);

    // init per-query lists
    if (tid < QB) {
        #pragma unroll
        for (int j = 0; j < LSEL; j++) {
            sKey[tid * LSTR + j] = CUDART_INF_F;
            sIdx[tid * LSTR + j] = 0x7fffffff;
        }
    }
    if (tid == 0) *sCnt = 0;

    // ---- load query tile: fp32 -> bf16, swizzled rows of 256B ----
    {
        const int row = tid >> 1, half = tid & 1;
        const float4* src = (const float4*)(xt + (size_t)(qbase + row) * DIM) + half * 16;
        const uint32_t rbase = sb + OFF_A + row * 256;
        const int sw = (row & 7);
        #pragma unroll
        for (int i = 0; i < 8; i++) {
            float4 v0 = src[2 * i], v1 = src[2 * i + 1];
            uint4 pk = make_uint4(bf2pack(v0.x, v0.y), bf2pack(v0.z, v0.w),
                                  bf2pack(v1.x, v1.y), bf2pack(v1.z, v1.w));
            int c16 = half * 8 + i;
            uint32_t addr = rbase + (((uint32_t)(c16 ^ sw)) << 4);
            asm volatile("st.shared.v4.b32 [%0], {%1,%2,%3,%4};"
                         :: "r"(addr), "r"(pk.x), "r"(pk.y), "r"(pk.z), "r"(pk.w) : "memory");
        }
    }

    auto prefetch = [&](uint32_t boff, uint32_t coff, int nbase) {
        const unsigned char* gb = (const unsigned char*)g_Xbf + (size_t)nbase * 256;
        #pragma unroll
        for (int i = 0; i < 4; i++) {
            int chunk = tid + i * NT;               // 0..1023
            int row = chunk >> 4, c16 = chunk & 15;
            uint32_t dst = sb + boff + row * 256 + (((uint32_t)(c16 ^ (row & 7))) << 4);
            cpa16(dst, gb + row * 256 + c16 * 16);
        }
        if (tid < NB) cpa4(sb + coff + tid * 4, &g_c[nbase + tid]);
        CP_COMMIT();
    };
    prefetch(OFF_B0, OFF_C0, sBeg);

    const int arow = (l & 15);
    const int brow = ((l >> 4) << 3) + (l & 7);
    const int ac16 = (l >> 4);
    const int bc16 = (l >> 3) & 1;
    const int sw7 = (l & 7);

    for (int t = 0; t < ntiles; t++) {
        const int cur = t & 1;
        const uint32_t boff = cur ? OFF_B1 : OFF_B0;
        const uint32_t coff = cur ? OFF_C1 : OFF_C0;
        if (t + 1 < ntiles) {
            prefetch(cur ? OFF_B0 : OFF_B1, cur ? OFF_C0 : OFF_C1, sBeg + (t + 1) * NB);
            CP_WAIT(1);
        } else {
            CP_WAIT(0);
        }
        __syncthreads();   // B/C ready; prev-tile list updates + cnt reset visible

        float acc[4][2][4];
        #pragma unroll
        for (int a = 0; a < 4; a++)
            #pragma unroll
            for (int b = 0; b < 2; b++)
                #pragma unroll
                for (int c = 0; c < 4; c++) acc[a][b][c] = 0.0f;

        #pragma unroll
        for (int ks = 0; ks < 8; ks++) {
            uint32_t af[4][4];
            #pragma unroll
            for (int mt = 0; mt < 4; mt++) {
                uint32_t addr = sb + OFF_A + (wm * 64 + mt * 16 + arow) * 256 +
                                (((uint32_t)((ac16 + 2 * ks) ^ sw7)) << 4);
                ldsm4(af[mt][0], af[mt][1], af[mt][2], af[mt][3], addr);
            }
            uint32_t bf[4];
            {
                uint32_t addr = sb + boff + (wn * 16 + brow) * 256 +
                                (((uint32_t)((bc16 + 2 * ks) ^ sw7)) << 4);
                ldsm4(bf[0], bf[1], bf[2], bf[3], addr);
            }
            #pragma unroll
            for (int mt = 0; mt < 4; mt++) {
                mma16816(acc[mt][0], af[mt], bf[0], bf[1]);
                mma16816(acc[mt][1], af[mt], bf[2], bf[3]);
            }
        }

        const float* sC = (const float*)(s + coff);
        float cc[2][2];
        #pragma unroll
        for (int j = 0; j < 2; j++) {
            const int v0 = wn * 16 + j * 8 + ((l & 3) << 1);
            cc[j][0] = sC[v0]; cc[j][1] = sC[v0 + 1];
        }
        const int nbase = sBeg + t * NB;

        // ---- load per-query thresholds (conflict-free: LSTR=9 coprime 32) ----
        float th[8];
        #pragma unroll
        for (int mt = 0; mt < 4; mt++)
            #pragma unroll
            for (int h = 0; h < 2; h++) {
                const int q = wm * 64 + mt * 16 + (l >> 2) + h * 8;
                th[2 * mt + h] = sKey[q * LSTR + LSEL - 1];
            }

        // ---- detection + push survivors ----
        unsigned pend = 0;
        #pragma unroll
        for (int mt = 0; mt < 4; mt++)
            #pragma unroll
            for (int e = 0; e < 4; e++) {
                const int ti = 2 * mt + (e >> 1);
                const int q  = wm * 64 + mt * 16 + (l >> 2) + ((e >> 1) << 3);
                #pragma unroll
                for (int j = 0; j < 2; j++) {
                    const int v = wn * 16 + j * 8 + ((l & 3) << 1) + (e & 1);
                    const float key = fmaf(-2.0f, acc[mt][j][e], cc[j][e & 1]);
                    const int n = nbase + v;
                    if (key <= th[ti] && n < nEnd) {
                        int pos = atomicAdd(sCnt, 1);
                        if (pos < CAP) { sBK[pos] = key; sBM[pos] = (q << 6) | v; }
                        else pend |= 1u << (mt * 8 + e * 2 + j);
                    }
                }
            }
        int any = __syncthreads_or((int)pend);

        // ---- owner drain (lock-free; broadcast reads) ----
        {
            int c = *sCnt; if (c > CAP) c = CAP;
            if (tid < QB) {
                float* mkq = sKey + tid * LSTR;
                int*   miq = sIdx + tid * LSTR;
                #pragma unroll 1
                for (int i = 0; i < c; i++) {
                    const int meta = sBM[i];
                    if ((meta >> 6) == tid)
                        list_insert(mkq, miq, sBK[i], nbase + (meta & 63));
                }
            }
        }
        __syncthreads();
        if (tid == 0) *sCnt = 0;

        // ---- overflow retry (rare; block-uniform) ----
        while (any) {
            __syncthreads();   // cnt reset + list updates visible
            #pragma unroll
            for (int mt = 0; mt < 4; mt++)
                #pragma unroll
                for (int h = 0; h < 2; h++) {
                    const int q = wm * 64 + mt * 16 + (l >> 2) + h * 8;
                    th[2 * mt + h] = sKey[q * LSTR + LSEL - 1];
                }
            #pragma unroll
            for (int mt = 0; mt < 4; mt++)
                #pragma unroll
                for (int e = 0; e < 4; e++) {
                    const int ti = 2 * mt + (e >> 1);
                    const int q  = wm * 64 + mt * 16 + (l >> 2) + ((e >> 1) << 3);
                    #pragma unroll
                    for (int j = 0; j < 2; j++) {
                        const unsigned bit = 1u << (mt * 8 + e * 2 + j);
                        if (pend & bit) {
                            const int v = wn * 16 + j * 8 + ((l & 3) << 1) + (e & 1);
                            const float key = fmaf(-2.0f, acc[mt][j][e], cc[j][e & 1]);
                            if (key <= th[ti]) {
                                int pos = atomicAdd(sCnt, 1);
                                if (pos < CAP) {
                                    sBK[pos] = key; sBM[pos] = (q << 6) | v;
                                    pend &= ~bit;
                                }
                            } else pend &= ~bit;
                        }
                    }
                }
            any = __syncthreads_or((int)pend);
            {
                int c = *sCnt; if (c > CAP) c = CAP;
                if (tid < QB) {
                    float* mkq = sKey + tid * LSTR;
                    int*   miq = sIdx + tid * LSTR;
                    #pragma unroll 1
                    for (int i = 0; i < c; i++) {
                        const int meta = sBM[i];
                        if ((meta >> 6) == tid)
                            list_insert(mkq, miq, sBK[i], nbase + (meta & 63));
                    }
                }
            }
            __syncthreads();
            if (tid == 0) *sCnt = 0;
        }
    }
    __syncthreads();

    // ---- write per-query lists ----
    if (tid < QB) {
        size_t o = ((size_t)(qbase + tid) * NSPLIT + split) * LSEL;
        #pragma unroll
        for (int j = 0; j < LSEL; j++) {
            g_keys[o + j] = sKey[tid * LSTR + j];
            g_idxs[o + j] = sIdx[tid * LSTR + j];
        }
    }
}

// ---------------- merge: approx top-20 of union -> exact rescore -> argmax ----
__global__ void __launch_bounds__(128)
merge_kernel(const float* __restrict__ xt, const float* __restrict__ X,
             const float* __restrict__ w, float* __restrict__ out, int B, int out_size) {
    __shared__ float sk[4][CAND];
    __shared__ int   si[4][CAND];
    __shared__ int   sn[4][SHORT];
    const int wid = threadIdx.x >> 5, lane = threadIdx.x & 31;
    const int b = blockIdx.x * 4 + wid;
    if (b >= B) return;

    for (int i = lane; i < CAND; i += 32) {
        sk[wid][i] = g_keys[(size_t)b * CAND + i];
        si[wid][i] = g_idxs[(size_t)b * CAND + i];
    }
    __syncwarp();

    for (int t = 0; t < SHORT; t++) {
        float bk = CUDART_INF_F; int bi = 0x7fffffff; int bp = -1;
        for (int i = lane; i < CAND; i += 32) {
            float kk = sk[wid][i]; int ii = si[wid][i];
            if (kk < bk || (kk == bk && ii < bi)) { bk = kk; bi = ii; bp = i; }
        }
        #pragma unroll
        for (int o = 16; o; o >>= 1) {
            float ok = __shfl_xor_sync(0xffffffffu, bk, o);
            int   oi = __shfl_xor_sync(0xffffffffu, bi, o);
            int   op = __shfl_xor_sync(0xffffffffu, bp, o);
            if (ok < bk || (ok == bk && oi < bi)) { bk = ok; bi = oi; bp = op; }
        }
        if (lane == 0) { sn[wid][t] = bi; sk[wid][bp] = CUDART_INF_F; }
        __syncwarp();
    }

    const float4 qv = *(const float4*)(xt + (size_t)b * DIM + lane * 4);
    float q2 = qv.x * qv.x + qv.y * qv.y + qv.z * qv.z + qv.w * qv.w;
    #pragma unroll
    for (int o = 16; o; o >>= 1) q2 += __shfl_xor_sync(0xffffffffu, q2, o);

    float keyA[SHORT], ddA[SHORT], wA[SHORT]; int nA[SHORT];
    const float wmax = g_wmax;
    for (int t = 0; t < SHORT; t++) {
        const int n = sn[wid][t];
        const float4 xv = *(const float4*)(X + (size_t)n * DIM + lane * 4);
        float dp = 0.0f, xp = 0.0f;
        dp = fmaf(qv.x, xv.x, dp); dp = fmaf(qv.y, xv.y, dp);
        dp = fmaf(qv.z, xv.z, dp); dp = fmaf(qv.w, xv.w, dp);
        xp = fmaf(xv.x, xv.x, xp); xp = fmaf(xv.y, xv.y, xp);
        xp = fmaf(xv.z, xv.z, xp); xp = fmaf(xv.w, xv.w, xp);
        #pragma unroll
        for (int o = 16; o; o >>= 1) {
            dp += __shfl_xor_sync(0xffffffffu, dp, o);
            xp += __shfl_xor_sync(0xffffffffu, xp, o);
        }
        if (lane == 0) {
            const float wn = w[n];
            const float dd = q2 - 2.0f * dp + xp;
            ddA[t] = dd; keyA[t] = dd + (wmax - wn); wA[t] = wn; nA[t] = n;
        }
    }

    if (lane == 0) {
        bool used[SHORT];
        #pragma unroll
        for (int t = 0; t < SHORT; t++) used[t] = false;
        float bestF = -CUDART_INF_F; int bestI = 0;
        for (int r = 0; r < KSEL; r++) {
            int pm = -1; float mkv = CUDART_INF_F; int miv = 0x7fffffff;
            for (int t = 0; t < SHORT; t++) {
                if (!used[t] && (keyA[t] < mkv || (keyA[t] == mkv && nA[t] < miv))) {
                    mkv = keyA[t]; miv = nA[t]; pm = t;
                }
            }
            if (pm < 0) break;
            used[pm] = true;
            const float f = wA[pm] - sqrtf(fmaxf(ddA[pm], 0.0f));
            if (f > bestF) { bestF = f; bestI = nA[pm]; }
        }
        out[b] = bestF;
        if (out_size >= 2 * B) out[B + b] = (float)bestI;
    }
}

// ---------------- entry ----------------
extern "C" void kernel_launch(void* const* d_in, const int* in_sizes, int n_in,
                              void* d_out, int out_size) {
    const float* xt = (const float*)d_in[0];
    const float* X  = (const float*)d_in[1];
    const float* w  = (const float*)d_in[2];
    const int B = in_sizes[0] / DIM;
    const int N = in_sizes[1] / DIM;

    const int per = (N + NSPLIT - 1) / NSPLIT;
    const int ntiles = (per + NB - 1) / NB;
    int padn = (NSPLIT - 1) * per + ntiles * NB;
    if (padn > MAXNP) padn = MAXNP;

    static bool once = false;
    if (!once) {
        cudaFuncSetAttribute(topk_kernel, cudaFuncAttributeMaxDynamicSharedMemorySize, SMEM_DYN);
        once = true;
    }

    init_kernel<<<1, 1>>>();
    wmax_kernel<<<160, 256>>>(w, N);
    prep_kernel<<<(padn + 255) / 256, 256>>>(X, w, N, padn);
    dim3 grid(B / QB, NSPLIT);
    topk_kernel<<<grid, NT, SMEM_DYN>>>(xt, per, ntiles);
    merge_kernel<<<(B + 3) / 4, 128>>>(xt, X, w, (float*)d_out, B, out_size);
}

// round 10
// speedup vs baseline: 2.7630x; 2.7630x over previous
#include <cuda_runtime.h>
#include <cuda_bf16.h>
#include <math_constants.h>
#include <cstdint>

#define DIM     128
#define QB      128
#define NB      64
#define NSPLIT  18
#define LSEL    8
#define SHORT   20
#define KSEL    10
#define MAXB    2048
#define MAXN    100000
#define MAXNP   100992
#define CAND    (NSPLIT * LSEL)
#define NT      256

// ---- dynamic smem layout ----
#define OFF_A    0            // 128x128 bf16 queries, swizzled       32KB
#define OFF_B0   32768        // candidate tile buf0 (64x256B)        16KB
#define OFF_B1   49152        // candidate tile buf1                  16KB
#define OFF_C0   65536        // 64 floats c[n] buf0
#define OFF_C1   65792        // 64 floats c[n] buf1
#define OFF_D    66048        // 128 x 64 fp32 keys (XOR-swizzled)    32KB
#define OFF_KEY  98816        // 256 * LSEL floats (private half-lists)
#define OFF_IDX  (OFF_KEY + NT * LSEL * 4)        // 256*LSEL uint16  4KB
#define OFF_TMIN (OFF_IDX + NT * LSEL * 2)        // 128*3 floats
#define SMEM_DYN (OFF_TMIN + 128 * 3 * 4 + 64)

// ---------------- device scratch ----------------
__device__ float          g_wmax;
__device__ float          g_c[MAXNP];
__device__ __nv_bfloat16  g_Xbf[(size_t)MAXNP * DIM];
__device__ float          g_keys[(size_t)MAXB * CAND];
__device__ int            g_idxs[(size_t)MAXB * CAND];

// ---------------- helpers ----------------
__device__ __forceinline__ uint32_t smem_u32(const void* p) {
    uint32_t a;
    asm("{ .reg .u64 t; cvta.to.shared.u64 t, %1; cvt.u32.u64 %0, t; }" : "=r"(a) : "l"(p));
    return a;
}
__device__ __forceinline__ void ldsm4(uint32_t& r0, uint32_t& r1, uint32_t& r2, uint32_t& r3,
                                      uint32_t addr) {
    asm volatile("ldmatrix.sync.aligned.m8n8.x4.shared.b16 {%0,%1,%2,%3}, [%4];"
                 : "=r"(r0), "=r"(r1), "=r"(r2), "=r"(r3) : "r"(addr));
}
__device__ __forceinline__ void mma16816(float* c, const uint32_t* a, uint32_t b0, uint32_t b1) {
    asm volatile("mma.sync.aligned.m16n8k16.row.col.f32.bf16.bf16.f32 "
                 "{%0,%1,%2,%3}, {%4,%5,%6,%7}, {%8,%9}, {%0,%1,%2,%3};"
                 : "+f"(c[0]), "+f"(c[1]), "+f"(c[2]), "+f"(c[3])
                 : "r"(a[0]), "r"(a[1]), "r"(a[2]), "r"(a[3]), "r"(b0), "r"(b1));
}
__device__ __forceinline__ void cpa16(uint32_t dst, const void* src) {
    asm volatile("cp.async.cg.shared.global [%0], [%1], 16;"
                 :: "r"(dst), "l"((size_t)__cvta_generic_to_global(src)) : "memory");
}
__device__ __forceinline__ void cpa4(uint32_t dst, const void* src) {
    asm volatile("cp.async.ca.shared.global [%0], [%1], 4;"
                 :: "r"(dst), "l"((size_t)__cvta_generic_to_global(src)) : "memory");
}
#define CP_COMMIT() asm volatile("cp.async.commit_group;" ::: "memory")
#define CP_WAIT(n)  asm volatile("cp.async.wait_group %0;" :: "n"(n) : "memory")

__device__ __forceinline__ uint32_t bf2pack(float x, float y) {
    __nv_bfloat162 v = __floats2bfloat162_rn(x, y);
    return *(uint32_t*)&v;
}
// 5-bit bijection: bit0->0, bits1-2->3-4, bits3-4->1-2
__device__ __forceinline__ int perm5(int x) {
    return (x & 1) | ((x & 6) << 2) | (((x >> 3) & 3) << 1);
}

// ---------------- init / wmax ----------------
__global__ void init_kernel() { g_wmax = 0.0f; }

__global__ void wmax_kernel(const float* __restrict__ w, int n) {
    float m = 0.0f;
    for (int i = blockIdx.x * blockDim.x + threadIdx.x; i < n; i += gridDim.x * blockDim.x)
        m = fmaxf(m, w[i]);
    #pragma unroll
    for (int o = 16; o; o >>= 1) m = fmaxf(m, __shfl_xor_sync(0xffffffffu, m, o));
    __shared__ float sm[32];
    int lane = threadIdx.x & 31, wid = threadIdx.x >> 5;
    if (lane == 0) sm[wid] = m;
    __syncthreads();
    if (wid == 0) {
        m = (lane < (int)(blockDim.x >> 5)) ? sm[lane] : 0.0f;
        #pragma unroll
        for (int o = 16; o; o >>= 1) m = fmaxf(m, __shfl_xor_sync(0xffffffffu, m, o));
        if (lane == 0) atomicMax((int*)&g_wmax, __float_as_int(m));  // vals >= 0
    }
}

// ---------------- prep: c[n] + bf16 convert, padded tail ----------------
__global__ void prep_kernel(const float* __restrict__ X, const float* __restrict__ w,
                            int n, int padn) {
    int i = blockIdx.x * blockDim.x + threadIdx.x;
    if (i >= padn) return;
    __nv_bfloat162* dst = (__nv_bfloat162*)(g_Xbf + (size_t)i * DIM);
    if (i >= n) {
        for (int j = 0; j < DIM / 2; j++) dst[j] = __floats2bfloat162_rn(0.f, 0.f);
        g_c[i] = CUDART_INF_F;
        return;
    }
    const float4* xr = (const float4*)(X + (size_t)i * DIM);
    float s = 0.0f;
    #pragma unroll
    for (int j = 0; j < DIM / 4; j++) {
        float4 v = xr[j];
        s = fmaf(v.x, v.x, s); s = fmaf(v.y, v.y, s);
        s = fmaf(v.z, v.z, s); s = fmaf(v.w, v.w, s);
        dst[2 * j + 0] = __floats2bfloat162_rn(v.x, v.y);
        dst[2 * j + 1] = __floats2bfloat162_rn(v.z, v.w);
    }
    g_c[i] = s + (g_wmax - w[i]);
}

// ---------------- main: M32N32 mma.sync GEMM + tmin-filtered scan ----------------
__global__ void __launch_bounds__(NT, 2)
topk_kernel(const float* __restrict__ xt, int per, int ntiles) {
    extern __shared__ unsigned char sraw[];
    unsigned char* s = sraw;
    const uint32_t sb = smem_u32(s);

    const int tid = threadIdx.x;
    const int l = tid & 31, wid = tid >> 5;
    const int wm = wid >> 1, wn = wid & 1;          // warp grid 4 x 2 (32 x 32 per warp)
    const int qbase = blockIdx.x * QB;
    const int split = blockIdx.y;
    const int sBeg = split * per;
    const int nEnd = sBeg + per;

    float*          sD    = (float*)(s + OFF_D);
    float*          sKey  = (float*)(s + OFF_KEY);
    unsigned short* sIdx  = (unsigned short*)(s + OFF_IDX);
    float*          sTmin = (float*)(s + OFF_TMIN);

    // scan identity: thread owns query (tid & 127), col half (tid >> 7) of 32
    const int sq = tid & 127;
    const int vbase = (tid >> 7) << 5;              // 0 or 32
    const int permq = perm5(sq & 31);
    float*          mk = sKey + tid * LSEL;
    unsigned short* mi = sIdx + tid * LSEL;
    #pragma unroll
    for (int j = 0; j < LSEL; j++) { mk[j] = CUDART_INF_F; mi[j] = 0xffff; }
    float thr = CUDART_INF_F;
    int   thrn = 0xffff;

    // ---- load query tile: fp32 -> bf16, swizzled rows of 256B ----
    {
        const int row = tid >> 1, half = tid & 1;
        const float4* src = (const float4*)(xt + (size_t)(qbase + row) * DIM) + half * 16;
        const uint32_t rbase = sb + OFF_A + row * 256;
        const int sw = (row & 7);
        #pragma unroll
        for (int i = 0; i < 8; i++) {
            float4 v0 = src[2 * i], v1 = src[2 * i + 1];
            uint4 pk = make_uint4(bf2pack(v0.x, v0.y), bf2pack(v0.z, v0.w),
                                  bf2pack(v1.x, v1.y), bf2pack(v1.z, v1.w));
            int c16 = half * 8 + i;
            uint32_t addr = rbase + (((uint32_t)(c16 ^ sw)) << 4);
            asm volatile("st.shared.v4.b32 [%0], {%1,%2,%3,%4};"
                         :: "r"(addr), "r"(pk.x), "r"(pk.y), "r"(pk.z), "r"(pk.w) : "memory");
        }
    }

    auto prefetch = [&](uint32_t boff, uint32_t coff, int nbase) {
        const unsigned char* gb = (const unsigned char*)g_Xbf + (size_t)nbase * 256;
        #pragma unroll
        for (int i = 0; i < 4; i++) {
            int chunk = tid + i * NT;               // 0..1023
            int row = chunk >> 4, c16 = chunk & 15;
            uint32_t dst = sb + boff + row * 256 + (((uint32_t)(c16 ^ (row & 7))) << 4);
            cpa16(dst, gb + row * 256 + c16 * 16);
        }
        if (tid < NB) cpa4(sb + coff + tid * 4, &g_c[nbase + tid]);
        CP_COMMIT();
    };
    prefetch(OFF_B0, OFF_C0, sBeg);

    const int arow = (l & 15);
    const int brow = ((l >> 4) << 3) + (l & 7);
    const int ac16 = (l >> 4);
    const int bc16 = (l >> 3) & 1;
    const int sw7 = (l & 7);

    for (int t = 0; t < ntiles; t++) {
        const int cur = t & 1;
        const uint32_t boff = cur ? OFF_B1 : OFF_B0;
        const uint32_t coff = cur ? OFF_C1 : OFF_C0;
        if (t + 1 < ntiles) {
            prefetch(cur ? OFF_B0 : OFF_B1, cur ? OFF_C0 : OFF_C1, sBeg + (t + 1) * NB);
            CP_WAIT(1);
        } else {
            CP_WAIT(0);
        }
        __syncthreads();   // B/C ready; prev-tile scan reads + list updates done

        float acc[2][4][4];
        #pragma unroll
        for (int a = 0; a < 2; a++)
            #pragma unroll
            for (int b = 0; b < 4; b++)
                #pragma unroll
                for (int c = 0; c < 4; c++) acc[a][b][c] = 0.0f;

        #pragma unroll
        for (int ks = 0; ks < 8; ks++) {
            uint32_t af[2][4];
            #pragma unroll
            for (int mt = 0; mt < 2; mt++) {
                uint32_t addr = sb + OFF_A + (wm * 32 + mt * 16 + arow) * 256 +
                                (((uint32_t)((ac16 + 2 * ks) ^ sw7)) << 4);
                ldsm4(af[mt][0], af[mt][1], af[mt][2], af[mt][3], addr);
            }
            uint32_t bf[2][4];
            #pragma unroll
            for (int pr = 0; pr < 2; pr++) {
                uint32_t addr = sb + boff + (wn * 32 + pr * 16 + brow) * 256 +
                                (((uint32_t)((bc16 + 2 * ks) ^ sw7)) << 4);
                ldsm4(bf[pr][0], bf[pr][1], bf[pr][2], bf[pr][3], addr);
            }
            #pragma unroll
            for (int mt = 0; mt < 2; mt++) {
                #pragma unroll
                for (int pr = 0; pr < 2; pr++) {
                    mma16816(acc[mt][2 * pr + 0], af[mt], bf[pr][0], bf[pr][1]);
                    mma16816(acc[mt][2 * pr + 1], af[mt], bf[pr][2], bf[pr][3]);
                }
            }
        }

        // ---- stage keys into sD + per-query tile-min reduction ----
        {
            const float* sC = (const float*)(s + coff);
            float cc[4][2];
            #pragma unroll
            for (int nt = 0; nt < 4; nt++) {
                const int v0 = wn * 32 + nt * 8 + ((l & 3) << 1);
                cc[nt][0] = sC[v0]; cc[nt][1] = sC[v0 + 1];
            }
            float tm[2][2];   // [mt][h] per-thread min over this thread's 8 keys of q
            #pragma unroll
            for (int mt = 0; mt < 2; mt++) { tm[mt][0] = CUDART_INF_F; tm[mt][1] = CUDART_INF_F; }
            #pragma unroll
            for (int mt = 0; mt < 2; mt++) {
                #pragma unroll
                for (int e = 0; e < 4; e++) {
                    const int h = e >> 1;
                    const int q = wm * 32 + mt * 16 + (l >> 2) + (h << 3);
                    const int pq = perm5(q & 31);
                    #pragma unroll
                    for (int nt = 0; nt < 4; nt++) {
                        const int v = wn * 32 + nt * 8 + ((l & 3) << 1) + (e & 1);
                        const float key = fmaf(-2.0f, acc[mt][nt][e], cc[nt][e & 1]);
                        sD[q * 64 + (v ^ pq)] = key;
                        tm[mt][h] = fminf(tm[mt][h], key);
                    }
                }
            }
            // reduce over the 4 lanes (l&3) sharing each query
            #pragma unroll
            for (int mt = 0; mt < 2; mt++)
                #pragma unroll
                for (int h = 0; h < 2; h++) {
                    float v = tm[mt][h];
                    v = fminf(v, __shfl_xor_sync(0xffffffffu, v, 1));
                    v = fminf(v, __shfl_xor_sync(0xffffffffu, v, 2));
                    tm[mt][h] = v;
                }
            if ((l & 3) == 0) {
                #pragma unroll
                for (int mt = 0; mt < 2; mt++)
                    #pragma unroll
                    for (int h = 0; h < 2; h++) {
                        const int q = wm * 32 + mt * 16 + (l >> 2) + (h << 3);
                        sTmin[q * 3 + wn] = tm[mt][h];
                    }
            }
        }
        __syncthreads();

        // ---- per-query scan with tile-min skip ----
        {
            const float tq = fminf(sTmin[sq * 3], sTmin[sq * 3 + 1]);
            if (tq <= thr) {
                const float* sDq = sD + sq * 64;
                #pragma unroll 4
                for (int v = vbase; v < vbase + 32; v++) {
                    const float key = sDq[v ^ permq];
                    const int code = t * NB + v;
                    if ((key < thr || (key == thr && code < thrn)) &&
                        (sBeg + code) < nEnd) {
                        int p = LSEL - 1;
                        #pragma unroll 1
                        while (p > 0 && (mk[p - 1] > key ||
                               (mk[p - 1] == key && mi[p - 1] > code))) {
                            mk[p] = mk[p - 1]; mi[p] = mi[p - 1]; p--;
                        }
                        mk[p] = key; mi[p] = (unsigned short)code;
                        thr = mk[LSEL - 1]; thrn = mi[LSEL - 1];
                    }
                }
            }
        }
        // (loop-top __syncthreads orders scan reads before next tile's staging)
    }
    __syncthreads();

    // ---- 2-way merge of sorted half-lists; write per-query result ----
    if (tid < QB) {
        const float* ka = sKey + tid * LSEL;
        const unsigned short* na = sIdx + tid * LSEL;
        const float* kb = sKey + (tid + 128) * LSEL;
        const unsigned short* nb = sIdx + (tid + 128) * LSEL;
        size_t o = ((size_t)(qbase + tid) * NSPLIT + split) * LSEL;
        int ia = 0, ib = 0;
        #pragma unroll
        for (int j = 0; j < LSEL; j++) {
            bool ta = (ka[ia] < kb[ib]) || (ka[ia] == kb[ib] && na[ia] <= nb[ib]);
            float k = ta ? ka[ia] : kb[ib];
            int   c = ta ? na[ia] : nb[ib];
            if (ta) ia++; else ib++;
            g_keys[o + j] = k;
            g_idxs[o + j] = (k == CUDART_INF_F) ? 0x7fffffff : (sBeg + c);
        }
    }
}

// ---------------- merge: approx top-20 of union -> exact rescore -> argmax ----
__global__ void __launch_bounds__(128)
merge_kernel(const float* __restrict__ xt, const float* __restrict__ X,
             const float* __restrict__ w, float* __restrict__ out, int B, int out_size) {
    __shared__ float sk[4][CAND];
    __shared__ int   si[4][CAND];
    __shared__ int   sn[4][SHORT];
    const int wid = threadIdx.x >> 5, lane = threadIdx.x & 31;
    const int b = blockIdx.x * 4 + wid;
    if (b >= B) return;

    for (int i = lane; i < CAND; i += 32) {
        sk[wid][i] = g_keys[(size_t)b * CAND + i];
        si[wid][i] = g_idxs[(size_t)b * CAND + i];
    }
    __syncwarp();

    for (int t = 0; t < SHORT; t++) {
        float bk = CUDART_INF_F; int bi = 0x7fffffff; int bp = -1;
        for (int i = lane; i < CAND; i += 32) {
            float kk = sk[wid][i]; int ii = si[wid][i];
            if (kk < bk || (kk == bk && ii < bi)) { bk = kk; bi = ii; bp = i; }
        }
        #pragma unroll
        for (int o = 16; o; o >>= 1) {
            float ok = __shfl_xor_sync(0xffffffffu, bk, o);
            int   oi = __shfl_xor_sync(0xffffffffu, bi, o);
            int   op = __shfl_xor_sync(0xffffffffu, bp, o);
            if (ok < bk || (ok == bk && oi < bi)) { bk = ok; bi = oi; bp = op; }
        }
        if (lane == 0) { sn[wid][t] = bi; sk[wid][bp] = CUDART_INF_F; }
        __syncwarp();
    }

    const float4 qv = *(const float4*)(xt + (size_t)b * DIM + lane * 4);
    float q2 = qv.x * qv.x + qv.y * qv.y + qv.z * qv.z + qv.w * qv.w;
    #pragma unroll
    for (int o = 16; o; o >>= 1) q2 += __shfl_xor_sync(0xffffffffu, q2, o);

    float keyA[SHORT], ddA[SHORT], wA[SHORT]; int nA[SHORT];
    const float wmax = g_wmax;
    for (int t = 0; t < SHORT; t++) {
        const int n = sn[wid][t];
        const float4 xv = *(const float4*)(X + (size_t)n * DIM + lane * 4);
        float dp = 0.0f, xp = 0.0f;
        dp = fmaf(qv.x, xv.x, dp); dp = fmaf(qv.y, xv.y, dp);
        dp = fmaf(qv.z, xv.z, dp); dp = fmaf(qv.w, xv.w, dp);
        xp = fmaf(xv.x, xv.x, xp); xp = fmaf(xv.y, xv.y, xp);
        xp = fmaf(xv.z, xv.z, xp); xp = fmaf(xv.w, xv.w, xp);
        #pragma unroll
        for (int o = 16; o; o >>= 1) {
            dp += __shfl_xor_sync(0xffffffffu, dp, o);
            xp += __shfl_xor_sync(0xffffffffu, xp, o);
        }
        if (lane == 0) {
            const float wn = w[n];
            const float dd = q2 - 2.0f * dp + xp;
            ddA[t] = dd; keyA[t] = dd + (wmax - wn); wA[t] = wn; nA[t] = n;
        }
    }

    if (lane == 0) {
        bool used[SHORT];
        #pragma unroll
        for (int t = 0; t < SHORT; t++) used[t] = false;
        float bestF = -CUDART_INF_F; int bestI = 0;
        for (int r = 0; r < KSEL; r++) {
            int pm = -1; float mkv = CUDART_INF_F; int miv = 0x7fffffff;
            for (int t = 0; t < SHORT; t++) {
                if (!used[t] && (keyA[t] < mkv || (keyA[t] == mkv && nA[t] < miv))) {
                    mkv = keyA[t]; miv = nA[t]; pm = t;
                }
            }
            if (pm < 0) break;
            used[pm] = true;
            const float f = wA[pm] - sqrtf(fmaxf(ddA[pm], 0.0f));
            if (f > bestF) { bestF = f; bestI = nA[pm]; }
        }
        out[b] = bestF;
        if (out_size >= 2 * B) out[B + b] = (float)bestI;
    }
}

// ---------------- entry ----------------
extern "C" void kernel_launch(void* const* d_in, const int* in_sizes, int n_in,
                              void* d_out, int out_size) {
    const float* xt = (const float*)d_in[0];
    const float* X  = (const float*)d_in[1];
    const float* w  = (const float*)d_in[2];
    const int B = in_sizes[0] / DIM;
    const int N = in_sizes[1] / DIM;

    const int per = (N + NSPLIT - 1) / NSPLIT;
    const int ntiles = (per + NB - 1) / NB;
    int padn = (NSPLIT - 1) * per + ntiles * NB;
    if (padn > MAXNP) padn = MAXNP;

    static bool once = false;
    if (!once) {
        cudaFuncSetAttribute(topk_kernel, cudaFuncAttributeMaxDynamicSharedMemorySize, SMEM_DYN);
        once = true;
    }

    init_kernel<<<1, 1>>>();
    wmax_kernel<<<160, 256>>>(w, N);
    prep_kernel<<<(padn + 255) / 256, 256>>>(X, w, N, padn);
    dim3 grid(B / QB, NSPLIT);
    topk_kernel<<<grid, NT, SMEM_DYN>>>(xt, per, ntiles);
    merge_kernel<<<(B + 3) / 4, 128>>>(xt, X, w, (float*)d_out, B, out_size);
}

// round 11
// speedup vs baseline: 3.3128x; 1.1990x over previous
#include <cuda_runtime.h>
#include <cuda_bf16.h>
#include <math_constants.h>
#include <cstdint>

#define DIM     128
#define QB      128
#define NB      64
#define NSPLIT  18
#define LSEL    8
#define SHORT   20
#define KSEL    10
#define MAXB    2048
#define MAXN    100000
#define MAXNP   100992
#define CAND    (NSPLIT * LSEL)
#define NT      256

// ---- dynamic smem layout ----
#define OFF_A    0            // 128x128 bf16 queries, swizzled       32KB
#define OFF_B0   32768        // candidate tile buf0 (64x256B)        16KB
#define OFF_B1   49152        // candidate tile buf1                  16KB
#define OFF_C0   65536        // 64 floats c[n] buf0
#define OFF_C1   65792        // 64 floats c[n] buf1
#define OFF_D    66048        // 128 x 64 fp32 keys (XOR-swizzled)    32KB
#define OFF_KEY  98816        // 256 * LSEL floats (private half-lists)
#define OFF_IDX  (OFF_KEY + NT * LSEL * 4)
#define SMEM_DYN (OFF_IDX + NT * LSEL * 4 + 128)

// ---------------- device scratch ----------------
__device__ float          g_wmax;
__device__ float          g_c[MAXNP];
__device__ __nv_bfloat16  g_Xbf[(size_t)MAXNP * DIM];
__device__ float          g_keys[(size_t)MAXB * CAND];
__device__ int            g_idxs[(size_t)MAXB * CAND];

// ---------------- helpers ----------------
__device__ __forceinline__ uint32_t smem_u32(const void* p) {
    uint32_t a;
    asm("{ .reg .u64 t; cvta.to.shared.u64 t, %1; cvt.u32.u64 %0, t; }" : "=r"(a) : "l"(p));
    return a;
}
__device__ __forceinline__ void ldsm4(uint32_t& r0, uint32_t& r1, uint32_t& r2, uint32_t& r3,
                                      uint32_t addr) {
    asm volatile("ldmatrix.sync.aligned.m8n8.x4.shared.b16 {%0,%1,%2,%3}, [%4];"
                 : "=r"(r0), "=r"(r1), "=r"(r2), "=r"(r3) : "r"(addr));
}
__device__ __forceinline__ void mma16816(float* c, const uint32_t* a, uint32_t b0, uint32_t b1) {
    asm volatile("mma.sync.aligned.m16n8k16.row.col.f32.bf16.bf16.f32 "
                 "{%0,%1,%2,%3}, {%4,%5,%6,%7}, {%8,%9}, {%0,%1,%2,%3};"
                 : "+f"(c[0]), "+f"(c[1]), "+f"(c[2]), "+f"(c[3])
                 : "r"(a[0]), "r"(a[1]), "r"(a[2]), "r"(a[3]), "r"(b0), "r"(b1));
}
__device__ __forceinline__ void cpa16(uint32_t dst, const void* src) {
    asm volatile("cp.async.cg.shared.global [%0], [%1], 16;"
                 :: "r"(dst), "l"((size_t)__cvta_generic_to_global(src)) : "memory");
}
__device__ __forceinline__ void cpa4(uint32_t dst, const void* src) {
    asm volatile("cp.async.ca.shared.global [%0], [%1], 4;"
                 :: "r"(dst), "l"((size_t)__cvta_generic_to_global(src)) : "memory");
}
#define CP_COMMIT() asm volatile("cp.async.commit_group;" ::: "memory")
#define CP_WAIT(n)  asm volatile("cp.async.wait_group %0;" :: "n"(n) : "memory")

__device__ __forceinline__ uint32_t bf2pack(float x, float y) {
    __nv_bfloat162 v = __floats2bfloat162_rn(x, y);
    return *(uint32_t*)&v;
}
// 5-bit bijection: bit0->0, bits1-2->3-4, bits3-4->1-2
__device__ __forceinline__ int perm5(int x) {
    return (x & 1) | ((x & 6) << 2) | (((x >> 3) & 3) << 1);
}

// ---------------- init / wmax ----------------
__global__ void init_kernel() { g_wmax = 0.0f; }

__global__ void wmax_kernel(const float* __restrict__ w, int n) {
    float m = 0.0f;
    for (int i = blockIdx.x * blockDim.x + threadIdx.x; i < n; i += gridDim.x * blockDim.x)
        m = fmaxf(m, w[i]);
    #pragma unroll
    for (int o = 16; o; o >>= 1) m = fmaxf(m, __shfl_xor_sync(0xffffffffu, m, o));
    __shared__ float sm[32];
    int lane = threadIdx.x & 31, wid = threadIdx.x >> 5;
    if (lane == 0) sm[wid] = m;
    __syncthreads();
    if (wid == 0) {
        m = (lane < (int)(blockDim.x >> 5)) ? sm[lane] : 0.0f;
        #pragma unroll
        for (int o = 16; o; o >>= 1) m = fmaxf(m, __shfl_xor_sync(0xffffffffu, m, o));
        if (lane == 0) atomicMax((int*)&g_wmax, __float_as_int(m));  // vals >= 0
    }
}

// ---------------- prep: c[n] + bf16 convert, padded tail ----------------
__global__ void prep_kernel(const float* __restrict__ X, const float* __restrict__ w,
                            int n, int padn) {
    int i = blockIdx.x * blockDim.x + threadIdx.x;
    if (i >= padn) return;
    __nv_bfloat162* dst = (__nv_bfloat162*)(g_Xbf + (size_t)i * DIM);
    if (i >= n) {
        for (int j = 0; j < DIM / 2; j++) dst[j] = __floats2bfloat162_rn(0.f, 0.f);
        g_c[i] = CUDART_INF_F;
        return;
    }
    const float4* xr = (const float4*)(X + (size_t)i * DIM);
    float s = 0.0f;
    #pragma unroll
    for (int j = 0; j < DIM / 4; j++) {
        float4 v = xr[j];
        s = fmaf(v.x, v.x, s); s = fmaf(v.y, v.y, s);
        s = fmaf(v.z, v.z, s); s = fmaf(v.w, v.w, s);
        dst[2 * j + 0] = __floats2bfloat162_rn(v.x, v.y);
        dst[2 * j + 1] = __floats2bfloat162_rn(v.z, v.w);
    }
    g_c[i] = s + (g_wmax - w[i]);
}

// ---------------- main: M32N32 mma.sync GEMM + lock-free staged top-LSEL ----
__global__ void __launch_bounds__(NT, 2)
topk_kernel(const float* __restrict__ xt, int per, int ntiles) {
    extern __shared__ unsigned char sraw[];
    unsigned char* s = sraw;
    const uint32_t sb = smem_u32(s);

    const int tid = threadIdx.x;
    const int l = tid & 31, wid = tid >> 5;
    const int wm = wid >> 1, wn = wid & 1;          // warp grid 4 x 2 (32 x 32 per warp)
    const int qbase = blockIdx.x * QB;
    const int split = blockIdx.y;
    const int sBeg = split * per;
    const int nEnd = sBeg + per;

    float* sD   = (float*)(s + OFF_D);
    float* sKey = (float*)(s + OFF_KEY);
    int*   sIdx = (int*)(s + OFF_IDX);

    // scan identity: thread owns query (tid & 127), col half (tid >> 7) of 32
    const int sq = tid & 127;
    const int vbase = (tid >> 7) << 5;              // 0 or 32
    const int permq = perm5(sq & 31);
    float* mk = sKey + tid * LSEL;
    int*   mi = sIdx + tid * LSEL;
    #pragma unroll
    for (int j = 0; j < LSEL; j++) { mk[j] = CUDART_INF_F; mi[j] = 0x7fffffff; }
    float thr = CUDART_INF_F;
    int   thrn = 0x7fffffff;

    // ---- load query tile: fp32 -> bf16, swizzled rows of 256B ----
    {
        const int row = tid >> 1, half = tid & 1;
        const float4* src = (const float4*)(xt + (size_t)(qbase + row) * DIM) + half * 16;
        const uint32_t rbase = sb + OFF_A + row * 256;
        const int sw = (row & 7);
        #pragma unroll
        for (int i = 0; i < 8; i++) {
            float4 v0 = src[2 * i], v1 = src[2 * i + 1];
            uint4 pk = make_uint4(bf2pack(v0.x, v0.y), bf2pack(v0.z, v0.w),
                                  bf2pack(v1.x, v1.y), bf2pack(v1.z, v1.w));
            int c16 = half * 8 + i;
            uint32_t addr = rbase + (((uint32_t)(c16 ^ sw)) << 4);
            asm volatile("st.shared.v4.b32 [%0], {%1,%2,%3,%4};"
                         :: "r"(addr), "r"(pk.x), "r"(pk.y), "r"(pk.z), "r"(pk.w) : "memory");
        }
    }

    auto prefetch = [&](uint32_t boff, uint32_t coff, int nbase) {
        const unsigned char* gb = (const unsigned char*)g_Xbf + (size_t)nbase * 256;
        #pragma unroll
        for (int i = 0; i < 4; i++) {
            int chunk = tid + i * NT;               // 0..1023
            int row = chunk >> 4, c16 = chunk & 15;
            uint32_t dst = sb + boff + row * 256 + (((uint32_t)(c16 ^ (row & 7))) << 4);
            cpa16(dst, gb + row * 256 + c16 * 16);
        }
        if (tid < NB) cpa4(sb + coff + tid * 4, &g_c[nbase + tid]);
        CP_COMMIT();
    };
    prefetch(OFF_B0, OFF_C0, sBeg);

    const int arow = (l & 15);
    const int brow = ((l >> 4) << 3) + (l & 7);
    const int ac16 = (l >> 4);
    const int bc16 = (l >> 3) & 1;
    const int sw7 = (l & 7);

    for (int t = 0; t < ntiles; t++) {
        const int cur = t & 1;
        const uint32_t boff = cur ? OFF_B1 : OFF_B0;
        const uint32_t coff = cur ? OFF_C1 : OFF_C0;
        if (t + 1 < ntiles) {
            prefetch(cur ? OFF_B0 : OFF_B1, cur ? OFF_C0 : OFF_C1, sBeg + (t + 1) * NB);
            CP_WAIT(1);
        } else {
            CP_WAIT(0);
        }
        __syncthreads();   // B/C ready; orders prev scan-reads before this stage-writes

        float acc[2][4][4];
        #pragma unroll
        for (int a = 0; a < 2; a++)
            #pragma unroll
            for (int b = 0; b < 4; b++)
                #pragma unroll
                for (int c = 0; c < 4; c++) acc[a][b][c] = 0.0f;

        #pragma unroll
        for (int ks = 0; ks < 8; ks++) {
            uint32_t af[2][4];
            #pragma unroll
            for (int mt = 0; mt < 2; mt++) {
                uint32_t addr = sb + OFF_A + (wm * 32 + mt * 16 + arow) * 256 +
                                (((uint32_t)((ac16 + 2 * ks) ^ sw7)) << 4);
                ldsm4(af[mt][0], af[mt][1], af[mt][2], af[mt][3], addr);
            }
            uint32_t bf[2][4];
            #pragma unroll
            for (int pr = 0; pr < 2; pr++) {
                uint32_t addr = sb + boff + (wn * 32 + pr * 16 + brow) * 256 +
                                (((uint32_t)((bc16 + 2 * ks) ^ sw7)) << 4);
                ldsm4(bf[pr][0], bf[pr][1], bf[pr][2], bf[pr][3], addr);
            }
            #pragma unroll
            for (int mt = 0; mt < 2; mt++) {
                #pragma unroll
                for (int pr = 0; pr < 2; pr++) {
                    mma16816(acc[mt][2 * pr + 0], af[mt], bf[pr][0], bf[pr][1]);
                    mma16816(acc[mt][2 * pr + 1], af[mt], bf[pr][2], bf[pr][3]);
                }
            }
        }

        // ---- stage keys into sD (rows of 64) with XOR-perm swizzle ----
        {
            const float* sC = (const float*)(s + coff);
            float cc[4][2];
            #pragma unroll
            for (int nt = 0; nt < 4; nt++) {
                const int v0 = wn * 32 + nt * 8 + ((l & 3) << 1);
                cc[nt][0] = sC[v0]; cc[nt][1] = sC[v0 + 1];
            }
            #pragma unroll
            for (int mt = 0; mt < 2; mt++) {
                #pragma unroll
                for (int e = 0; e < 4; e++) {
                    const int q = wm * 32 + mt * 16 + (l >> 2) + ((e >> 1) << 3);
                    const int pq = perm5(q & 31);
                    #pragma unroll
                    for (int nt = 0; nt < 4; nt++) {
                        const int v = wn * 32 + nt * 8 + ((l & 3) << 1) + (e & 1);
                        const float key = fmaf(-2.0f, acc[mt][nt][e], cc[nt][e & 1]);
                        sD[q * 64 + (v ^ pq)] = key;
                    }
                }
            }
        }
        __syncthreads();

        // ---- per-query scan: thread owns query sq, cols [vbase, vbase+32) ----
        {
            const int nbase = sBeg + t * NB;
            const float* sDq = sD + sq * 64;
            #pragma unroll 4
            for (int v = vbase; v < vbase + 32; v++) {
                const float key = sDq[v ^ permq];
                const int n = nbase + v;
                if ((key < thr || (key == thr && n < thrn)) && n < nEnd) {
                    int p = LSEL - 1;
                    #pragma unroll 1
                    while (p > 0 && (mk[p - 1] > key || (mk[p - 1] == key && mi[p - 1] > n))) {
                        mk[p] = mk[p - 1]; mi[p] = mi[p - 1]; p--;
                    }
                    mk[p] = key; mi[p] = n;
                    thr = mk[LSEL - 1]; thrn = mi[LSEL - 1];
                }
            }
        }
        // (loop-top __syncthreads orders scan reads before next tile's staging)
    }
    __syncthreads();

    // ---- 2-way merge of sorted half-lists; write per-query result ----
    if (tid < QB) {
        const float* ka = sKey + tid * LSEL;         const int* na = sIdx + tid * LSEL;
        const float* kb = sKey + (tid + 128) * LSEL; const int* nb = sIdx + (tid + 128) * LSEL;
        size_t o = ((size_t)(qbase + tid) * NSPLIT + split) * LSEL;
        int ia = 0, ib = 0;
        #pragma unroll
        for (int j = 0; j < LSEL; j++) {
            bool ta = (ka[ia] < kb[ib]) || (ka[ia] == kb[ib] && na[ia] <= nb[ib]);
            if (ta) { g_keys[o + j] = ka[ia]; g_idxs[o + j] = na[ia]; ia++; }
            else    { g_keys[o + j] = kb[ib]; g_idxs[o + j] = nb[ib]; ib++; }
        }
    }
}

// ---------------- merge: approx top-20 of union -> exact rescore -> argmax ----
__global__ void __launch_bounds__(128)
merge_kernel(const float* __restrict__ xt, const float* __restrict__ X,
             const float* __restrict__ w, float* __restrict__ out, int B, int out_size) {
    __shared__ float sk[4][CAND];
    __shared__ int   si[4][CAND];
    __shared__ int   sn[4][SHORT];
    const int wid = threadIdx.x >> 5, lane = threadIdx.x & 31;
    const int b = blockIdx.x * 4 + wid;
    if (b >= B) return;

    for (int i = lane; i < CAND; i += 32) {
        sk[wid][i] = g_keys[(size_t)b * CAND + i];
        si[wid][i] = g_idxs[(size_t)b * CAND + i];
    }
    __syncwarp();

    for (int t = 0; t < SHORT; t++) {
        float bk = CUDART_INF_F; int bi = 0x7fffffff; int bp = -1;
        for (int i = lane; i < CAND; i += 32) {
            float kk = sk[wid][i]; int ii = si[wid][i];
            if (kk < bk || (kk == bk && ii < bi)) { bk = kk; bi = ii; bp = i; }
        }
        #pragma unroll
        for (int o = 16; o; o >>= 1) {
            float ok = __shfl_xor_sync(0xffffffffu, bk, o);
            int   oi = __shfl_xor_sync(0xffffffffu, bi, o);
            int   op = __shfl_xor_sync(0xffffffffu, bp, o);
            if (ok < bk || (ok == bk && oi < bi)) { bk = ok; bi = oi; bp = op; }
        }
        if (lane == 0) { sn[wid][t] = bi; sk[wid][bp] = CUDART_INF_F; }
        __syncwarp();
    }

    const float4 qv = *(const float4*)(xt + (size_t)b * DIM + lane * 4);
    float q2 = qv.x * qv.x + qv.y * qv.y + qv.z * qv.z + qv.w * qv.w;
    #pragma unroll
    for (int o = 16; o; o >>= 1) q2 += __shfl_xor_sync(0xffffffffu, q2, o);

    float keyA[SHORT], ddA[SHORT], wA[SHORT]; int nA[SHORT];
    const float wmax = g_wmax;
    for (int t = 0; t < SHORT; t++) {
        const int n = sn[wid][t];
        const float4 xv = *(const float4*)(X + (size_t)n * DIM + lane * 4);
        float dp = 0.0f, xp = 0.0f;
        dp = fmaf(qv.x, xv.x, dp); dp = fmaf(qv.y, xv.y, dp);
        dp = fmaf(qv.z, xv.z, dp); dp = fmaf(qv.w, xv.w, dp);
        xp = fmaf(xv.x, xv.x, xp); xp = fmaf(xv.y, xv.y, xp);
        xp = fmaf(xv.z, xv.z, xp); xp = fmaf(xv.w, xv.w, xp);
        #pragma unroll
        for (int o = 16; o; o >>= 1) {
            dp += __shfl_xor_sync(0xffffffffu, dp, o);
            xp += __shfl_xor_sync(0xffffffffu, xp, o);
        }
        if (lane == 0) {
            const float wn = w[n];
            const float dd = q2 - 2.0f * dp + xp;
            ddA[t] = dd; keyA[t] = dd + (wmax - wn); wA[t] = wn; nA[t] = n;
        }
    }

    if (lane == 0) {
        bool used[SHORT];
        #pragma unroll
        for (int t = 0; t < SHORT; t++) used[t] = false;
        float bestF = -CUDART_INF_F; int bestI = 0;
        for (int r = 0; r < KSEL; r++) {
            int pm = -1; float mkv = CUDART_INF_F; int miv = 0x7fffffff;
            for (int t = 0; t < SHORT; t++) {
                if (!used[t] && (keyA[t] < mkv || (keyA[t] == mkv && nA[t] < miv))) {
                    mkv = keyA[t]; miv = nA[t]; pm = t;
                }
            }
            if (pm < 0) break;
            used[pm] = true;
            const float f = wA[pm] - sqrtf(fmaxf(ddA[pm], 0.0f));
            if (f > bestF) { bestF = f; bestI = nA[pm]; }
        }
        out[b] = bestF;
        if (out_size >= 2 * B) out[B + b] = (float)bestI;
    }
}

// ---------------- entry ----------------
extern "C" void kernel_launch(void* const* d_in, const int* in_sizes, int n_in,
                              void* d_out, int out_size) {
    const float* xt = (const float*)d_in[0];
    const float* X  = (const float*)d_in[1];
    const float* w  = (const float*)d_in[2];
    const int B = in_sizes[0] / DIM;
    const int N = in_sizes[1] / DIM;

    const int per = (N + NSPLIT - 1) / NSPLIT;
    const int ntiles = (per + NB - 1) / NB;
    int padn = (NSPLIT - 1) * per + ntiles * NB;
    if (padn > MAXNP) padn = MAXNP;

    static bool once = false;
    if (!once) {
        cudaFuncSetAttribute(topk_kernel, cudaFuncAttributeMaxDynamicSharedMemorySize, SMEM_DYN);
        once = true;
    }

    init_kernel<<<1, 1>>>();
    wmax_kernel<<<160, 256>>>(w, N);
    prep_kernel<<<(padn + 255) / 256, 256>>>(X, w, N, padn);
    dim3 grid(B / QB, NSPLIT);
    topk_kernel<<<grid, NT, SMEM_DYN>>>(xt, per, ntiles);
    merge_kernel<<<(B + 3) / 4, 128>>>(xt, X, w, (float*)d_out, B, out_size);
}